// round 8
// baseline (speedup 1.0000x reference)
#include <cuda_runtime.h>
#include <cstdint>

// Spiking MLP, exact integer path:
//   s2 = ((x @ W1^T >= 1) @ W2^T >= 1)
// Weights as 5 balanced base-256 int8 digits of rint(w * 2^37); activations {0,1} int8.
// Each limb GEMM exact in s32 (mma.m16n8k32.s8); limbs combined exactly in double.

static const int M_BATCH = 4096;
static const int IN_DIM  = 3136;
static const int FEAT    = 6272;
static const int OUT_DIM = 500;
static const int OUT_PAD = 512;

#define WSCALE 137438953472.0   /* 2^37 */

// ---------------- device scratch (allocation-free rule) ----------------
__device__ int8_t g_x8 [4096ull * 3136ull];                 // x as 0/1 s8
__device__ int8_t g_w1L[5ull * 6272ull * 3136ull];          // W1 limbs (slice 0 = most significant)
__device__ int8_t g_s18[4096ull * 6272ull];                 // hidden spikes s8
__device__ int8_t g_w2L[5ull * 512ull * 6272ull];           // W2 limbs, N padded to 512

// ---------------- asm helpers ----------------
__device__ __forceinline__ uint32_t smem_u32(const void* p) {
    uint32_t a;
    asm("{ .reg .u64 t; cvta.to.shared.u64 t, %1; cvt.u32.u64 %0, t; }" : "=r"(a) : "l"(p));
    return a;
}
#define CP_ASYNC16(smem, gmem) \
    asm volatile("cp.async.cg.shared.global [%0], [%1], 16;" :: "r"(smem), "l"(gmem) : "memory")
#define CP_COMMIT() asm volatile("cp.async.commit_group;" ::: "memory")
#define CP_WAIT1()  asm volatile("cp.async.wait_group 1;" ::: "memory")
#define CP_WAIT0()  asm volatile("cp.async.wait_group 0;" ::: "memory")
#define LDMATRIX_X4(r0, r1, r2, r3, a) \
    asm volatile("ldmatrix.sync.aligned.m8n8.x4.shared.b16 {%0,%1,%2,%3}, [%4];" \
                 : "=r"(r0), "=r"(r1), "=r"(r2), "=r"(r3) : "r"(a))
#define MMAS8(d0,d1,d2,d3, a0,a1,a2,a3, b0,b1) \
    asm volatile("mma.sync.aligned.m16n8k32.row.col.s32.s8.s8.s32 " \
                 "{%0,%1,%2,%3}, {%4,%5,%6,%7}, {%8,%9}, {%0,%1,%2,%3};" \
                 : "+r"(d0), "+r"(d1), "+r"(d2), "+r"(d3) \
                 : "r"(a0), "r"(a1), "r"(a2), "r"(a3), "r"(b0), "r"(b1))

// ---------------- conversion kernels ----------------
__global__ void cvt_x8_kernel(const float* __restrict__ in, int8_t* __restrict__ out, int n4) {
    int i = blockIdx.x * blockDim.x + threadIdx.x;
    if (i < n4) {
        float4 v = ((const float4*)in)[i];
        char4 c;
        c.x = (v.x >= 0.5f) ? 1 : 0;
        c.y = (v.y >= 0.5f) ? 1 : 0;
        c.z = (v.z >= 0.5f) ? 1 : 0;
        c.w = (v.w >= 0.5f) ? 1 : 0;
        ((char4*)out)[i] = c;
    }
}

// W -> 5 balanced base-256 digits of rint(w * 2^37). Slice 0 = most significant digit.
__global__ void cvt_wlimbs_kernel(const float* __restrict__ w, int8_t* __restrict__ out,
                                  int rows_real, int cols, size_t limb_stride, int n_pad) {
    int i = blockIdx.x * blockDim.x + threadIdx.x;
    if (i < n_pad) {
        int row = i / cols;
        int col = i - row * cols;
        float v = (row < rows_real) ? w[(size_t)row * cols + col] : 0.0f;
        long long W = llrint((double)v * WSCALE);
#pragma unroll
        for (int j = 0; j < 5; j++) {
            int r = (int)(W & 255);
            if (r >= 128) r -= 256;
            out[(size_t)(4 - j) * limb_stride + i] = (int8_t)r;
            W = (W - r) >> 8;
        }
    }
}

// ---------------- exact s8 limb-GEMM with fused threshold ----------------
// spikes = ( (A01 @ sum_j 256^(4-j) * BL[j]^T) * 2^-37 >= 1 )
// A [M,K] s8 0/1 row-major; BL slice j: [Npad,K] s8 row-major.
// CTA 128(M) x 64(N), BK=64. 16 warps = 4(M) x 4(N); warp tile 32x16 = 2m x 2n atoms.
// smem/stage: A 128x64 (8KB) + 5 x B 64x64 (20KB) = 28KB; 3 stages.
#define STAGE_BYTES 28672
#define SMEM_BYTES  (3 * STAGE_BYTES)

__global__ void __launch_bounds__(512, 1)
spike_imma_kernel(const int8_t* __restrict__ A,
                  const int8_t* __restrict__ B,        // limb 0 base
                  size_t limbStride,
                  int K, int Npad,
                  int8_t* __restrict__ out8,           // s8 [M, Npad] if is_s8
                  float*  __restrict__ outf,           // f32 [M, Nreal] else
                  int Nreal, int is_s8)
{
    extern __shared__ __align__(1024) char smem[];
    const uint32_t sbase = smem_u32(smem);

    const int tid  = threadIdx.x;
    const int wrp  = tid >> 5;
    const int lane = tid & 31;
    const int wm   = wrp >> 2;            // 0..3 -> m base wm*32
    const int wn   = wrp & 3;             // 0..3 -> n base wn*16
    const int m0   = blockIdx.y * 128;
    const int n0   = blockIdx.x * 64;

    const int NIT = K >> 6;               // BK=64 stages

    // ---- cp.async mapping (per stage): A 512 chunks, B 1280 chunks of 16B ----
    const int a_row = tid >> 2;           // 0..127
    const int a_ch  = tid & 3;
    const uint32_t a_soff = a_row * 64 + ((a_ch ^ ((a_row >> 1) & 3)) << 4);
    const int8_t* a_gbase = A + (size_t)(m0 + a_row) * K + a_ch * 16;

    // ---- ldmatrix addressing ----
    const int r15  = lane & 15;
    const int hi   = lane >> 4;           // 0/1 -> +16B within the 32B k-step
    const int lxor = (r15 >> 1) & 3;      // swizzle xor (bases are multiples of 16)
    const int arow0 = wm * 32 + r15;      // mi=0
    const int arow1 = wm * 32 + 16 + r15; // mi=1
    const int brow  = wn * 16 + r15;

    int S[5][2][2][4];
#pragma unroll
    for (int l = 0; l < 5; l++)
#pragma unroll
        for (int mi = 0; mi < 2; mi++)
#pragma unroll
            for (int nj = 0; nj < 2; nj++)
#pragma unroll
                for (int r = 0; r < 4; r++) S[l][mi][nj][r] = 0;

    // ---- stage load helper ----
    auto load_stage = [&](int cidx) {
        const int k0 = cidx << 6;
        const uint32_t sb = sbase + (uint32_t)(cidx % 3) * STAGE_BYTES;
        CP_ASYNC16(sb + a_soff, a_gbase + k0);
        for (int id = tid; id < 1280; id += 512) {
            int l = id >> 8;
            int rc = id & 255;
            int row = rc >> 2, ch = rc & 3;
            uint32_t soff = 8192 + l * 4096 + row * 64 + ((ch ^ ((row >> 1) & 3)) << 4);
            const int8_t* g = B + (size_t)l * limbStride + (size_t)(n0 + row) * K + k0 + ch * 16;
            CP_ASYNC16(sb + soff, g);
        }
        CP_COMMIT();
    };

    // prologue: stages 0, 1
    load_stage(0);
    load_stage(1);

    for (int c = 0; c < NIT; c++) {
        if (c < NIT - 1) { CP_WAIT1(); } else { CP_WAIT0(); }
        __syncthreads();

        const uint32_t stA = sbase + (uint32_t)(c % 3) * STAGE_BYTES;
        const uint32_t stB = stA + 8192;

#pragma unroll
        for (int step = 0; step < 2; step++) {
            const int ch = step * 2 + hi;
            uint32_t a0[4], a1[4];
            LDMATRIX_X4(a0[0], a0[1], a0[2], a0[3],
                        stA + arow0 * 64 + ((ch ^ lxor) << 4));
            LDMATRIX_X4(a1[0], a1[1], a1[2], a1[3],
                        stA + arow1 * 64 + ((ch ^ lxor) << 4));
#pragma unroll
            for (int l = 0; l < 5; l++) {
                uint32_t q0, q1, q2, q3;
                LDMATRIX_X4(q0, q1, q2, q3,
                            stB + l * 4096 + brow * 64 + ((ch ^ lxor) << 4));
                // atom nj=0: {q0,q2}; nj=1: {q1,q3}
                MMAS8(S[l][0][0][0], S[l][0][0][1], S[l][0][0][2], S[l][0][0][3],
                      a0[0], a0[1], a0[2], a0[3], q0, q2);
                MMAS8(S[l][0][1][0], S[l][0][1][1], S[l][0][1][2], S[l][0][1][3],
                      a0[0], a0[1], a0[2], a0[3], q1, q3);
                MMAS8(S[l][1][0][0], S[l][1][0][1], S[l][1][0][2], S[l][1][0][3],
                      a1[0], a1[1], a1[2], a1[3], q0, q2);
                MMAS8(S[l][1][1][0], S[l][1][1][1], S[l][1][1][2], S[l][1][1][3],
                      a1[0], a1[1], a1[2], a1[3], q1, q3);
            }
        }

        if (c + 2 < NIT) load_stage(c + 2);
    }

    // ---- exact limb combine + threshold epilogue ----
    const int qrow = lane >> 2;
    const int qcol = (lane & 3) * 2;
#pragma unroll
    for (int mi = 0; mi < 2; mi++) {
#pragma unroll
        for (int nj = 0; nj < 2; nj++) {
            float sp[4];
#pragma unroll
            for (int r = 0; r < 4; r++) {
                // slice 0 = most significant digit: Horner in double, exact (< 2^53)
                double V = (double)S[0][mi][nj][r];
                V = V * 256.0 + (double)S[1][mi][nj][r];
                V = V * 256.0 + (double)S[2][mi][nj][r];
                V = V * 256.0 + (double)S[3][mi][nj][r];
                V = V * 256.0 + (double)S[4][mi][nj][r];
                sp[r] = (V >= WSCALE) ? 1.0f : 0.0f;
            }
            const int row0 = m0 + wm * 32 + mi * 16 + qrow;
            const int colb = n0 + wn * 16 + nj * 8 + qcol;
            if (is_s8) {
                uint16_t v01 = (uint16_t)((sp[0] != 0.f ? 1 : 0) | ((sp[1] != 0.f ? 1 : 0) << 8));
                uint16_t v23 = (uint16_t)((sp[2] != 0.f ? 1 : 0) | ((sp[3] != 0.f ? 1 : 0) << 8));
                *(uint16_t*)(out8 + (size_t)row0 * Npad + colb)       = v01;
                *(uint16_t*)(out8 + (size_t)(row0 + 8) * Npad + colb) = v23;
            } else {
                if (colb < Nreal) {
                    outf[(size_t)row0 * Nreal + colb]       = sp[0];
                    outf[(size_t)(row0 + 8) * Nreal + colb] = sp[2];
                }
                if (colb + 1 < Nreal) {
                    outf[(size_t)row0 * Nreal + colb + 1]       = sp[1];
                    outf[(size_t)(row0 + 8) * Nreal + colb + 1] = sp[3];
                }
            }
        }
    }
}

// ---------------- host launch ----------------
extern "C" void kernel_launch(void* const* d_in, const int* in_sizes, int n_in,
                              void* d_out, int out_size)
{
    const float* x  = (const float*)d_in[0];   // [4096, 3136]
    const float* W1 = (const float*)d_in[1];   // [6272, 3136]
    const float* W2 = (const float*)d_in[2];   // [500, 6272]
    float* out = (float*)d_out;                // [4096, 500]

    int8_t *x8, *w1L, *s18, *w2L;
    cudaGetSymbolAddress((void**)&x8,  g_x8);
    cudaGetSymbolAddress((void**)&w1L, g_w1L);
    cudaGetSymbolAddress((void**)&s18, g_s18);
    cudaGetSymbolAddress((void**)&w2L, g_w2L);

    cudaFuncSetAttribute(spike_imma_kernel,
                         cudaFuncAttributeMaxDynamicSharedMemorySize, SMEM_BYTES);

    const size_t W1_STRIDE = (size_t)FEAT * IN_DIM;      // 19,668,992
    const size_t W2_STRIDE = (size_t)OUT_PAD * FEAT;     // 3,211,264

    // conversions
    {
        int n4 = (M_BATCH * IN_DIM) / 4;
        cvt_x8_kernel<<<(n4 + 255) / 256, 256>>>(x, x8, n4);
        int n1 = FEAT * IN_DIM;
        cvt_wlimbs_kernel<<<(n1 + 255) / 256, 256>>>(W1, w1L, FEAT, IN_DIM, W1_STRIDE, n1);
        int n2 = OUT_PAD * FEAT;
        cvt_wlimbs_kernel<<<(n2 + 255) / 256, 256>>>(W2, w2L, OUT_DIM, FEAT, W2_STRIDE, n2);
    }

    // GEMM1: s1 = spike(x @ W1^T), M=4096, N=6272, K=3136
    {
        dim3 grid(FEAT / 64, M_BATCH / 128);   // (98, 32)
        spike_imma_kernel<<<grid, 512, SMEM_BYTES>>>(
            x8, w1L, W1_STRIDE, IN_DIM, FEAT, s18, nullptr, FEAT, 1);
    }
    // GEMM2: out = spike(s1 @ W2^T), M=4096, Npad=512, K=6272, Nreal=500
    {
        dim3 grid(OUT_PAD / 64, M_BATCH / 128);  // (8, 32)
        spike_imma_kernel<<<grid, 512, SMEM_BYTES>>>(
            s18, w2L, W2_STRIDE, FEAT, OUT_PAD, nullptr, out, OUT_DIM, 0);
    }
}

// round 10
// speedup vs baseline: 1.4844x; 1.4844x over previous
#include <cuda_runtime.h>
#include <cstdint>

// Spiking MLP: s2 = ((x @ W1^T >= 1) @ W2^T >= 1)
// Packed-fp32 (fma.rn.f32x2 / FFMA2) SIMT GEMM, bit-identical math to the
// proven round-1 fp32 kernel (same per-output ascending-k FMA sequence).

#define BM 128
#define BN 128
#define BK 8
#define TM 8
#define TN 8
#define NTHREADS 256

static const int M_BATCH = 4096;
static const int FEAT    = 6272;
static const int IN_DIM  = 3136;
static const int OUT_DIM = 500;

// hidden spikes scratch: 4096 * 6272 floats = 102.8 MB
__device__ float g_s1[4096ull * 6272ull];

// d(.f32x2) += a * b   (two independent IEEE fp32 FMAs)
#define FMA2(d, a, b) \
    asm("fma.rn.f32x2 %0, %1, %2, %0;" : "+l"(d) : "l"(a), "l"(b))

__device__ __forceinline__ unsigned long long pack_dup(float x) {
    unsigned long long r;
    unsigned int u = __float_as_uint(x);
    asm("mov.b64 %0, {%1, %1};" : "=l"(r) : "r"(u));
    return r;
}

// C = threshold(A @ B^T), A [M,K] row-major, B [N,K] row-major.
// M multiple of BM, K multiple of BK and 4; N may be ragged.
__global__ __launch_bounds__(NTHREADS, 2)
void spike_gemm2x_kernel(const float* __restrict__ A,
                         const float* __restrict__ B,
                         float* __restrict__ C,
                         int M, int N, int K)
{
    __shared__ float As[BK][BM];
    __shared__ float Bs[BK][BN];

    const int tid = threadIdx.x;
    const int tx  = tid % 16;          // column group
    const int ty  = tid / 16;          // row group
    const int m0  = blockIdx.y * BM;
    const int n0  = blockIdx.x * BN;

    // global-load mapping: 256 threads cover 128 rows x 8 k, float4 each
    const int lr = tid >> 1;           // tile row 0..127
    const int lc = (tid & 1) * 4;      // k offset 0 or 4

    // acc as packed f32x2 pairs: acc2[i][j2] = (C[i][2j2], C[i][2j2+1])
    unsigned long long acc2[TM][TN / 2];
#pragma unroll
    for (int i = 0; i < TM; i++)
#pragma unroll
        for (int j = 0; j < TN / 2; j++) acc2[i][j] = 0ull;   // (0.0f, 0.0f)

    const float* Aptr = A + (size_t)(m0 + lr) * K + lc;
    const bool   brow_ok = (n0 + lr) < N;
    const float* Bptr = B + (size_t)(n0 + lr) * K + lc;

    // prologue: prefetch chunk 0 into registers
    float4 av = *(const float4*)(Aptr);
    float4 bv = brow_ok ? *(const float4*)(Bptr) : make_float4(0.f, 0.f, 0.f, 0.f);

    for (int k0 = 0; k0 < K; k0 += BK) {
        // stage current chunk to smem (transposed: As[k][m])
        As[lc + 0][lr] = av.x;
        As[lc + 1][lr] = av.y;
        As[lc + 2][lr] = av.z;
        As[lc + 3][lr] = av.w;
        Bs[lc + 0][lr] = bv.x;
        Bs[lc + 1][lr] = bv.y;
        Bs[lc + 2][lr] = bv.z;
        Bs[lc + 3][lr] = bv.w;
        __syncthreads();

        // prefetch next chunk (gmem latency overlaps compute below)
        if (k0 + BK < K) {
            av = *(const float4*)(Aptr + k0 + BK);
            bv = brow_ok ? *(const float4*)(Bptr + k0 + BK)
                         : make_float4(0.f, 0.f, 0.f, 0.f);
        }

#pragma unroll
        for (int kk = 0; kk < BK; kk++) {
            float4 a0 = *(const float4*)&As[kk][ty * TM];
            float4 a1 = *(const float4*)&As[kk][ty * TM + 4];
            // b pairs read pre-packed (consecutive floats = one f32x2)
            ulonglong2 bq0 = *(const ulonglong2*)&Bs[kk][tx * TN];
            ulonglong2 bq1 = *(const ulonglong2*)&Bs[kk][tx * TN + 4];

            float a[TM];
            a[0] = a0.x; a[1] = a0.y; a[2] = a0.z; a[3] = a0.w;
            a[4] = a1.x; a[5] = a1.y; a[6] = a1.z; a[7] = a1.w;
#pragma unroll
            for (int i = 0; i < TM; i++) {
                unsigned long long aa = pack_dup(a[i]);
                FMA2(acc2[i][0], aa, bq0.x);
                FMA2(acc2[i][1], aa, bq0.y);
                FMA2(acc2[i][2], aa, bq1.x);
                FMA2(acc2[i][3], aa, bq1.y);
            }
        }
        __syncthreads();
    }

    // fused threshold epilogue (hard-reset IF neuron, single step, v0 = 0)
#pragma unroll
    for (int i = 0; i < TM; i++) {
        const int row = m0 + ty * TM + i;
#pragma unroll
        for (int j2 = 0; j2 < TN / 2; j2++) {
            const unsigned long long p = acc2[i][j2];
            const float vlo = __uint_as_float((unsigned int)(p & 0xFFFFFFFFull));
            const float vhi = __uint_as_float((unsigned int)(p >> 32));
            const int col = n0 + tx * TN + 2 * j2;
            if (col < N)
                C[(size_t)row * N + col] = (vlo >= 1.0f) ? 1.0f : 0.0f;
            if (col + 1 < N)
                C[(size_t)row * N + col + 1] = (vhi >= 1.0f) ? 1.0f : 0.0f;
        }
    }
}

extern "C" void kernel_launch(void* const* d_in, const int* in_sizes, int n_in,
                              void* d_out, int out_size)
{
    const float* x  = (const float*)d_in[0];   // [4096, 3136]
    const float* W1 = (const float*)d_in[1];   // [6272, 3136]
    const float* W2 = (const float*)d_in[2];   // [500, 6272]
    float* out = (float*)d_out;                // [4096, 500]

    float* s1 = nullptr;
    cudaGetSymbolAddress((void**)&s1, g_s1);

    // GEMM1: s1 = threshold(x @ W1^T)   M=4096, N=6272, K=3136
    {
        dim3 grid(FEAT / BN, M_BATCH / BM);   // (49, 32)
        spike_gemm2x_kernel<<<grid, NTHREADS>>>(x, W1, s1, M_BATCH, FEAT, IN_DIM);
    }
    // GEMM2: out = threshold(s1 @ W2^T)  M=4096, N=500, K=6272
    {
        dim3 grid((OUT_DIM + BN - 1) / BN, M_BATCH / BM);  // (4, 32)
        spike_gemm2x_kernel<<<grid, NTHREADS>>>(s1, W2, out, M_BATCH, OUT_DIM, FEAT);
    }
}